// round 4
// baseline (speedup 1.0000x reference)
#include <cuda_runtime.h>

typedef unsigned long long ull;

#define BB 16
#define CC 64
#define NN 4096      // H*W
#define NP 1024      // pooled positions (32*32)

// ---------------- scratch (device globals; no allocation) ----------------
__device__ float g_theta[BB * NN * 8];   // [b][n][8]
__device__ float g_phi[BB * NP * 8];     // [b][p][8]
__device__ float g_gv[BB * NP * 32];     // [b][p][32]

// ---------------- f32x2 helpers ----------------
__device__ __forceinline__ ull pack2(float lo, float hi) {
    ull r; asm("mov.b64 %0, {%1,%2};" : "=l"(r) : "f"(lo), "f"(hi)); return r;
}
__device__ __forceinline__ void unpack2(ull v, float& lo, float& hi) {
    asm("mov.b64 {%0,%1}, %2;" : "=f"(lo), "=f"(hi) : "l"(v));
}
__device__ __forceinline__ void fma2(ull& d, ull a, ull b) {
    asm("fma.rn.f32x2 %0, %1, %2, %0;" : "+l"(d) : "l"(a), "l"(b));
}
__device__ __forceinline__ ull mul2(ull a, ull b) {
    ull d; asm("mul.rn.f32x2 %0, %1, %2;" : "=l"(d) : "l"(a), "l"(b)); return d;
}

// =========================================================================
// Kernel 1: 1x1 conv projections + 2x2 maxpool. (unchanged — not hot)
// =========================================================================
__global__ void __launch_bounds__(128, 1)
proj_kernel(const float* __restrict__ x,
            const float* __restrict__ tw,
            const float* __restrict__ pw,
            const float* __restrict__ gw)
{
    __shared__ float ws[64 * 48];
    for (int i = threadIdx.x; i < 64 * 48; i += 128) {
        int k = i / 48, o = i % 48;
        float v;
        if (o < 8)        v = tw[o * 64 + k];
        else if (o < 16)  v = pw[(o - 8) * 64 + k];
        else              v = gw[(o - 16) * 64 + k];
        ws[i] = v;
    }
    __syncthreads();

    int p  = blockIdx.x * 128 + threadIdx.x;
    int b  = p >> 10;
    int pp = p & 1023;
    int hp = pp >> 5, wp = pp & 31;

    const float* xb = x + (size_t)b * CC * NN;

    float best[40];
#pragma unroll
    for (int c = 0; c < 40; c++) best[c] = -1e30f;

    for (int dy = 0; dy < 2; dy++) {
        ull acc0[24], acc1[24];
#pragma unroll
        for (int c = 0; c < 24; c++) { acc0[c] = 0ull; acc1[c] = 0ull; }

        const float* xrow = xb + (2 * hp + dy) * 64 + 2 * wp;
#pragma unroll 4
        for (int k = 0; k < 64; k++) {
            float2 xv = *(const float2*)(xrow + (size_t)k * NN);
            ull a0 = pack2(xv.x, xv.x);
            ull a1 = pack2(xv.y, xv.y);
            const ull* w2 = (const ull*)(ws + k * 48);
#pragma unroll
            for (int c = 0; c < 24; c++) {
                ull w = w2[c];
                fma2(acc0[c], a0, w);
                fma2(acc1[c], a1, w);
            }
        }

        int n0 = (2 * hp + dy) * 64 + 2 * wp;
        {
            float t[8];
            unpack2(acc0[0], t[0], t[1]); unpack2(acc0[1], t[2], t[3]);
            unpack2(acc0[2], t[4], t[5]); unpack2(acc0[3], t[6], t[7]);
            float4* dst = (float4*)(g_theta + ((size_t)b * NN + n0) * 8);
            dst[0] = make_float4(t[0], t[1], t[2], t[3]);
            dst[1] = make_float4(t[4], t[5], t[6], t[7]);
            unpack2(acc1[0], t[0], t[1]); unpack2(acc1[1], t[2], t[3]);
            unpack2(acc1[2], t[4], t[5]); unpack2(acc1[3], t[6], t[7]);
            float4* dst1 = (float4*)(g_theta + ((size_t)b * NN + n0 + 1) * 8);
            dst1[0] = make_float4(t[0], t[1], t[2], t[3]);
            dst1[1] = make_float4(t[4], t[5], t[6], t[7]);
        }
#pragma unroll
        for (int c = 4; c < 24; c++) {
            float u, v;
            unpack2(acc0[c], u, v);
            best[2 * c - 8]     = fmaxf(best[2 * c - 8], u);
            best[2 * c - 8 + 1] = fmaxf(best[2 * c - 8 + 1], v);
            unpack2(acc1[c], u, v);
            best[2 * c - 8]     = fmaxf(best[2 * c - 8], u);
            best[2 * c - 8 + 1] = fmaxf(best[2 * c - 8 + 1], v);
        }
    }

    {
        float4* dst = (float4*)(g_phi + ((size_t)b * NP + pp) * 8);
        dst[0] = make_float4(best[0], best[1], best[2], best[3]);
        dst[1] = make_float4(best[4], best[5], best[6], best[7]);
    }
    {
        float4* dst = (float4*)(g_gv + ((size_t)b * NP + pp) * 32);
#pragma unroll
        for (int c = 0; c < 8; c++)
            dst[c] = make_float4(best[8 + 4 * c], best[9 + 4 * c],
                                 best[10 + 4 * c], best[11 + 4 * c]);
    }
}

// =========================================================================
// Kernel 2: fused attention + o-projection + residual.
// Grid (8 tiles, 16 batches), 256 threads, 2 queries/thread (512 q/CTA).
// All smem reads as 128-bit LDS (broadcast) to halve crossbar pressure.
// =========================================================================
#define THREADS 256
#define QPT 2
#define SMEM_PHI  0
#define SMEM_G    8192
#define SMEM_OW   (8192 + 32768)
#define SMEM_FLTS (8192 + 32768 + 2048)
#define SMEM_BYTES (SMEM_FLTS * 4)

__global__ void __launch_bounds__(THREADS, 1)
attn_kernel(const float* __restrict__ x,
            const float* __restrict__ ow,
            const float* __restrict__ gamma_p,
            float* __restrict__ out)
{
    extern __shared__ float sm[];
    float* phi_s = sm + SMEM_PHI;
    float* g_s   = sm + SMEM_G;
    float* ow_s  = sm + SMEM_OW;

    const int tid  = threadIdx.x;
    const int b    = blockIdx.y;
    const int tile = blockIdx.x;

    // ---- stage smem (straight float4 copies; layouts match) ----
    {
        const float4* ps = (const float4*)(g_phi + (size_t)b * NP * 8);
        float4* pd = (float4*)phi_s;
        for (int i = tid; i < NP * 8 / 4; i += THREADS) pd[i] = ps[i];
        const float4* gs = (const float4*)(g_gv + (size_t)b * NP * 32);
        float4* gd = (float4*)g_s;
        for (int i = tid; i < NP * 32 / 4; i += THREADS) gd[i] = gs[i];
        const float4* os = (const float4*)ow;
        float4* od = (float4*)ow_s;
        for (int i = tid; i < 64 * 32 / 4; i += THREADS) od[i] = os[i];
    }
    __syncthreads();

    const int q0 = tile * 512 + tid;   // queries q0 + 256*i, i<QPT

    ull th[QPT][4];
#pragma unroll
    for (int i = 0; i < QPT; i++) {
        const ull* tp = (const ull*)(g_theta + ((size_t)b * NN + q0 + i * THREADS) * 8);
        th[i][0] = tp[0]; th[i][1] = tp[1]; th[i][2] = tp[2]; th[i][3] = tp[3];
    }

    ull acc[QPT][16];
#pragma unroll
    for (int i = 0; i < QPT; i++)
#pragma unroll
        for (int c = 0; c < 16; c++) acc[i][c] = 0ull;
    float den[QPT];
#pragma unroll
    for (int i = 0; i < QPT; i++) den[i] = 0.f;

    const ulonglong2* phi4 = (const ulonglong2*)phi_s;   // [m][2]  (4 ch pairs)
    const ulonglong2* g4   = (const ulonglong2*)g_s;     // [m][8]  (16 ch pairs)

#pragma unroll 4
    for (int m = 0; m < NP; m++) {
        ulonglong2 pA = phi4[2 * m];
        ulonglong2 pB = phi4[2 * m + 1];

        ull ea[QPT];
#pragma unroll
        for (int i = 0; i < QPT; i++) {
            ull s2 = mul2(th[i][0], pA.x);
            fma2(s2, th[i][1], pA.y);
            fma2(s2, th[i][2], pB.x);
            fma2(s2, th[i][3], pB.y);
            float slo, shi;
            unpack2(s2, slo, shi);
            float e = __expf(slo + shi);   // logits bounded; max-free softmax OK
            den[i] += e;
            ea[i] = pack2(e, e);
        }

        const ulonglong2* gm = g4 + m * 8;
#pragma unroll
        for (int k = 0; k < 8; k++) {
            ulonglong2 gv = gm[k];
#pragma unroll
            for (int i = 0; i < QPT; i++) {
                fma2(acc[i][2 * k],     ea[i], gv.x);
                fma2(acc[i][2 * k + 1], ea[i], gv.y);
            }
        }
    }

    // ---- epilogue: o = o_w @ attn ; out = gamma*o + x ----
    const float gamma = *gamma_p;
    const ulonglong2* ow4 = (const ulonglong2*)ow_s;     // [j][8]
#pragma unroll
    for (int i = 0; i < QPT; i++) {
        const int q = q0 + i * THREADS;
        const float sc = gamma / den[i];
        const float* xq = x + ((size_t)b * CC) * NN + q;
        float*       oq = out + ((size_t)b * CC) * NN + q;
        for (int j = 0; j < 64; j++) {
            const ulonglong2* wj = ow4 + j * 8;
            ulonglong2 w0 = wj[0];
            ull o2 = mul2(w0.x, acc[i][0]);
            fma2(o2, w0.y, acc[i][1]);
#pragma unroll
            for (int k = 1; k < 8; k++) {
                ulonglong2 wk = wj[k];
                fma2(o2, wk.x, acc[i][2 * k]);
                fma2(o2, wk.y, acc[i][2 * k + 1]);
            }
            float oa, ob;
            unpack2(o2, oa, ob);
            oq[(size_t)j * NN] = fmaf(sc, oa + ob, xq[(size_t)j * NN]);
        }
    }
}

// =========================================================================
extern "C" void kernel_launch(void* const* d_in, const int* in_sizes, int n_in,
                              void* d_out, int out_size)
{
    const float* x     = (const float*)d_in[0];
    const float* tw    = (const float*)d_in[1];
    const float* pw    = (const float*)d_in[2];
    const float* gw    = (const float*)d_in[3];
    const float* ow    = (const float*)d_in[4];
    const float* gamma = (const float*)d_in[5];
    float* out = (float*)d_out;

    cudaFuncSetAttribute(attn_kernel,
                         cudaFuncAttributeMaxDynamicSharedMemorySize, SMEM_BYTES);

    proj_kernel<<<BB * NP / 128, 128>>>(x, tw, pw, gw);
    attn_kernel<<<dim3(8, BB), THREADS, SMEM_BYTES>>>(x, ow, gamma, out);
}

// round 5
// speedup vs baseline: 1.0759x; 1.0759x over previous
#include <cuda_runtime.h>

typedef unsigned long long ull;

#define BB 16
#define CC 64
#define NN 4096      // H*W
#define NP 1024      // pooled positions (32*32)

// ---------------- scratch (device globals; no allocation) ----------------
__device__ float g_theta[BB * NN * 8];   // [b][n][8]
__device__ float g_phi[BB * NP * 8];     // [b][p][8]
__device__ float g_gv[BB * NP * 32];     // [b][p][32]

// ---------------- f32x2 helpers ----------------
__device__ __forceinline__ ull pack2(float lo, float hi) {
    ull r; asm("mov.b64 %0, {%1,%2};" : "=l"(r) : "f"(lo), "f"(hi)); return r;
}
__device__ __forceinline__ void unpack2(ull v, float& lo, float& hi) {
    asm("mov.b64 {%0,%1}, %2;" : "=f"(lo), "=f"(hi) : "l"(v));
}
__device__ __forceinline__ void fma2(ull& d, ull a, ull b) {
    asm("fma.rn.f32x2 %0, %1, %2, %0;" : "+l"(d) : "l"(a), "l"(b));
}
__device__ __forceinline__ ull mul2(ull a, ull b) {
    ull d; asm("mul.rn.f32x2 %0, %1, %2;" : "=l"(d) : "l"(a), "l"(b)); return d;
}
__device__ __forceinline__ ull add2(ull a, ull b) {
    ull d; asm("add.rn.f32x2 %0, %1, %2;" : "=l"(d) : "l"(a), "l"(b)); return d;
}
__device__ __forceinline__ float ex2f(float x) {
    float r; asm("ex2.approx.f32 %0, %1;" : "=f"(r) : "f"(x)); return r;
}

// =========================================================================
// Kernel 1: 1x1 conv projections + 2x2 maxpool. (unchanged — not hot)
// =========================================================================
__global__ void __launch_bounds__(128, 1)
proj_kernel(const float* __restrict__ x,
            const float* __restrict__ tw,
            const float* __restrict__ pw,
            const float* __restrict__ gw)
{
    __shared__ float ws[64 * 48];
    for (int i = threadIdx.x; i < 64 * 48; i += 128) {
        int k = i / 48, o = i % 48;
        float v;
        if (o < 8)        v = tw[o * 64 + k];
        else if (o < 16)  v = pw[(o - 8) * 64 + k];
        else              v = gw[(o - 16) * 64 + k];
        ws[i] = v;
    }
    __syncthreads();

    int p  = blockIdx.x * 128 + threadIdx.x;
    int b  = p >> 10;
    int pp = p & 1023;
    int hp = pp >> 5, wp = pp & 31;

    const float* xb = x + (size_t)b * CC * NN;

    float best[40];
#pragma unroll
    for (int c = 0; c < 40; c++) best[c] = -1e30f;

    for (int dy = 0; dy < 2; dy++) {
        ull acc0[24], acc1[24];
#pragma unroll
        for (int c = 0; c < 24; c++) { acc0[c] = 0ull; acc1[c] = 0ull; }

        const float* xrow = xb + (2 * hp + dy) * 64 + 2 * wp;
#pragma unroll 4
        for (int k = 0; k < 64; k++) {
            float2 xv = *(const float2*)(xrow + (size_t)k * NN);
            ull a0 = pack2(xv.x, xv.x);
            ull a1 = pack2(xv.y, xv.y);
            const ull* w2 = (const ull*)(ws + k * 48);
#pragma unroll
            for (int c = 0; c < 24; c++) {
                ull w = w2[c];
                fma2(acc0[c], a0, w);
                fma2(acc1[c], a1, w);
            }
        }

        int n0 = (2 * hp + dy) * 64 + 2 * wp;
        {
            float t[8];
            unpack2(acc0[0], t[0], t[1]); unpack2(acc0[1], t[2], t[3]);
            unpack2(acc0[2], t[4], t[5]); unpack2(acc0[3], t[6], t[7]);
            float4* dst = (float4*)(g_theta + ((size_t)b * NN + n0) * 8);
            dst[0] = make_float4(t[0], t[1], t[2], t[3]);
            dst[1] = make_float4(t[4], t[5], t[6], t[7]);
            unpack2(acc1[0], t[0], t[1]); unpack2(acc1[1], t[2], t[3]);
            unpack2(acc1[2], t[4], t[5]); unpack2(acc1[3], t[6], t[7]);
            float4* dst1 = (float4*)(g_theta + ((size_t)b * NN + n0 + 1) * 8);
            dst1[0] = make_float4(t[0], t[1], t[2], t[3]);
            dst1[1] = make_float4(t[4], t[5], t[6], t[7]);
        }
#pragma unroll
        for (int c = 4; c < 24; c++) {
            float u, v;
            unpack2(acc0[c], u, v);
            best[2 * c - 8]     = fmaxf(best[2 * c - 8], u);
            best[2 * c - 8 + 1] = fmaxf(best[2 * c - 8 + 1], v);
            unpack2(acc1[c], u, v);
            best[2 * c - 8]     = fmaxf(best[2 * c - 8], u);
            best[2 * c - 8 + 1] = fmaxf(best[2 * c - 8 + 1], v);
        }
    }

    {
        float4* dst = (float4*)(g_phi + ((size_t)b * NP + pp) * 8);
        dst[0] = make_float4(best[0], best[1], best[2], best[3]);
        dst[1] = make_float4(best[4], best[5], best[6], best[7]);
    }
    {
        float4* dst = (float4*)(g_gv + ((size_t)b * NP + pp) * 32);
#pragma unroll
        for (int c = 0; c < 8; c++)
            dst[c] = make_float4(best[8 + 4 * c], best[9 + 4 * c],
                                 best[10 + 4 * c], best[11 + 4 * c]);
    }
}

// =========================================================================
// Kernel 2: fused attention + o-projection + residual.
// Grid (8 tiles, 16 batches), 256 threads.
// KEY SPLIT: warps 0-3 do keys [0,512), warps 4-7 do keys [512,1024),
// each half covering ALL 512 queries at QPT=4 (g loads amortized 2x better).
// Partials merged through smem (g region reused), then full-CTA epilogue.
// =========================================================================
#define THREADS 256
#define QPT 4
#define SMEM_PHI  0
#define SMEM_G    8192
#define SMEM_OW   (8192 + 32768)
#define SMEM_FLTS (8192 + 32768 + 2048)
#define SMEM_BYTES (SMEM_FLTS * 4)
#define L2E 1.4426950408889634f

__global__ void __launch_bounds__(THREADS, 1)
attn_kernel(const float* __restrict__ x,
            const float* __restrict__ ow,
            const float* __restrict__ gamma_p,
            float* __restrict__ out)
{
    extern __shared__ float sm[];
    float* phi_s = sm + SMEM_PHI;
    float* g_s   = sm + SMEM_G;
    float* ow_s  = sm + SMEM_OW;

    const int tid  = threadIdx.x;
    const int b    = blockIdx.y;
    const int tile = blockIdx.x;
    const int grp  = tid >> 7;        // 0 or 1 (key-range half)
    const int gtid = tid & 127;

    // ---- stage smem (straight float4 copies; layouts match) ----
    {
        const float4* ps = (const float4*)(g_phi + (size_t)b * NP * 8);
        float4* pd = (float4*)phi_s;
        for (int i = tid; i < NP * 8 / 4; i += THREADS) pd[i] = ps[i];
        const float4* gs = (const float4*)(g_gv + (size_t)b * NP * 32);
        float4* gd = (float4*)g_s;
        for (int i = tid; i < NP * 32 / 4; i += THREADS) gd[i] = gs[i];
        const float4* os = (const float4*)ow;
        float4* od = (float4*)ow_s;
        for (int i = tid; i < 64 * 32 / 4; i += THREADS) od[i] = os[i];
    }
    __syncthreads();

    const int q0 = tile * 512 + gtid;   // queries q0 + 128*i, i<QPT (both groups)

    // theta, pre-scaled by log2(e) so exp is a bare ex2
    ull th[QPT][4];
    {
        const ull l2e2 = pack2(L2E, L2E);
#pragma unroll
        for (int i = 0; i < QPT; i++) {
            const ull* tp = (const ull*)(g_theta + ((size_t)b * NN + q0 + i * 128) * 8);
            th[i][0] = mul2(tp[0], l2e2); th[i][1] = mul2(tp[1], l2e2);
            th[i][2] = mul2(tp[2], l2e2); th[i][3] = mul2(tp[3], l2e2);
        }
    }

    ull acc[QPT][16];
#pragma unroll
    for (int i = 0; i < QPT; i++)
#pragma unroll
        for (int c = 0; c < 16; c++) acc[i][c] = 0ull;
    float den[QPT];
#pragma unroll
    for (int i = 0; i < QPT; i++) den[i] = 0.f;

    const ulonglong2* phi4 = (const ulonglong2*)phi_s;   // [m][2]
    const ulonglong2* g4   = (const ulonglong2*)g_s;     // [m][8]

    const int m0 = grp * 512;
#pragma unroll 4
    for (int m = m0; m < m0 + 512; m++) {
        ulonglong2 pA = phi4[2 * m];
        ulonglong2 pB = phi4[2 * m + 1];

        ull ea[QPT];
#pragma unroll
        for (int i = 0; i < QPT; i++) {
            ull s2 = mul2(th[i][0], pA.x);
            fma2(s2, th[i][1], pA.y);
            fma2(s2, th[i][2], pB.x);
            fma2(s2, th[i][3], pB.y);
            float slo, shi;
            unpack2(s2, slo, shi);
            float e = ex2f(slo + shi);     // theta pre-scaled by log2e
            den[i] += e;
            ea[i] = pack2(e, e);
        }

        const ulonglong2* gm = g4 + m * 8;
#pragma unroll
        for (int k = 0; k < 8; k++) {
            ulonglong2 gv = gm[k];
#pragma unroll
            for (int i = 0; i < QPT; i++) {
                fma2(acc[i][2 * k],     ea[i], gv.x);
                fma2(acc[i][2 * k + 1], ea[i], gv.y);
            }
        }
    }

    // ---- merge partials through smem (g region reused; conflict-free) ----
    __syncthreads();                      // everyone done reading phi/g
    ull*   accU  = (ull*)g_s;             // [ (i*16+c)*256 + grp*128 + gtid ]
    float* den_s = phi_s;                 // [ grp*512 + i*128 + gtid ]
#pragma unroll
    for (int i = 0; i < QPT; i++) {
#pragma unroll
        for (int c = 0; c < 16; c++)
            accU[(i * 16 + c) * 256 + grp * 128 + gtid] = acc[i][c];
        den_s[grp * 512 + i * 128 + gtid] = den[i];
    }
    __syncthreads();

    // ---- epilogue: all 256 threads, 2 queries each ----
    const float gamma = *gamma_p;
    const ulonglong2* ow4 = (const ulonglong2*)ow_s;     // [j][8]
#pragma unroll
    for (int jq = 0; jq < 2; jq++) {
        const int p = tid + jq * 256;      // query position within tile [0,512)
        const int ip = p >> 7, lp = p & 127;

        ull am[16];
#pragma unroll
        for (int c = 0; c < 16; c++) {
            ull a0 = accU[(ip * 16 + c) * 256 + lp];
            ull a1 = accU[(ip * 16 + c) * 256 + 128 + lp];
            am[c] = add2(a0, a1);
        }
        const float dm = den_s[p] + den_s[512 + p];
        const float sc = gamma / dm;

        const int q = tile * 512 + p;
        const float* xq = x + ((size_t)b * CC) * NN + q;
        float*       oq = out + ((size_t)b * CC) * NN + q;
        for (int j = 0; j < 64; j++) {
            const ulonglong2* wj = ow4 + j * 8;
            ulonglong2 w0 = wj[0];
            ull o2 = mul2(w0.x, am[0]);
            fma2(o2, w0.y, am[1]);
#pragma unroll
            for (int k = 1; k < 8; k++) {
                ulonglong2 wk = wj[k];
                fma2(o2, wk.x, am[2 * k]);
                fma2(o2, wk.y, am[2 * k + 1]);
            }
            float oa, ob;
            unpack2(o2, oa, ob);
            oq[(size_t)j * NN] = fmaf(sc, oa + ob, xq[(size_t)j * NN]);
        }
    }
}

// =========================================================================
extern "C" void kernel_launch(void* const* d_in, const int* in_sizes, int n_in,
                              void* d_out, int out_size)
{
    const float* x     = (const float*)d_in[0];
    const float* tw    = (const float*)d_in[1];
    const float* pw    = (const float*)d_in[2];
    const float* gw    = (const float*)d_in[3];
    const float* ow    = (const float*)d_in[4];
    const float* gamma = (const float*)d_in[5];
    float* out = (float*)d_out;

    cudaFuncSetAttribute(attn_kernel,
                         cudaFuncAttributeMaxDynamicSharedMemorySize, SMEM_BYTES);

    proj_kernel<<<BB * NP / 128, 128>>>(x, tw, pw, gw);
    attn_kernel<<<dim3(8, BB), THREADS, SMEM_BYTES>>>(x, ow, gamma, out);
}

// round 9
// speedup vs baseline: 2.7337x; 2.5407x over previous
#include <cuda_runtime.h>
#include <cuda_bf16.h>
#include <cstdint>

typedef unsigned long long ull;
typedef unsigned int uint;

#define BB 16
#define CC 64
#define NN 4096      // H*W
#define NP 1024      // pooled positions
#define L2E 1.4426950408889634f

// ---------------- scratch (device globals; no allocation) ----------------
__device__ __nv_bfloat16 g_theta_b[BB * NN * 8];   // [b][n][8]   bf16, pre-scaled by log2e
__device__ __nv_bfloat16 g_phi_b[BB * NP * 8];     // [b][p][8]   bf16
__device__ __nv_bfloat16 g_gT_b[BB * 32 * NP];     // [b][ch][p]  bf16 (transposed)

// ---------------- f32x2 / misc helpers ----------------
__device__ __forceinline__ ull pack2(float lo, float hi) {
    ull r; asm("mov.b64 %0, {%1,%2};" : "=l"(r) : "f"(lo), "f"(hi)); return r;
}
__device__ __forceinline__ void unpack2(ull v, float& lo, float& hi) {
    asm("mov.b64 {%0,%1}, %2;" : "=f"(lo), "=f"(hi) : "l"(v));
}
__device__ __forceinline__ void fma2(ull& d, ull a, ull b) {
    asm("fma.rn.f32x2 %0, %1, %2, %0;" : "+l"(d) : "l"(a), "l"(b));
}
__device__ __forceinline__ ull mul2(ull a, ull b) {
    ull d; asm("mul.rn.f32x2 %0, %1, %2;" : "=l"(d) : "l"(a), "l"(b)); return d;
}
__device__ __forceinline__ float ex2f(float x) {
    float r; asm("ex2.approx.f32 %0, %1;" : "=f"(r) : "f"(x)); return r;
}
// pack two f32 -> bf16x2 (first arg -> low half)
__device__ __forceinline__ uint bf2(float lo, float hi) {
    uint r; asm("cvt.rn.bf16x2.f32 %0, %1, %2;" : "=r"(r) : "f"(hi), "f"(lo)); return r;
}
__device__ __forceinline__ float shflx(float v, int m) {
    float r; asm("shfl.sync.bfly.b32 %0, %1, %2, 0x1F, 0xFFFFFFFF;" : "=f"(r) : "f"(v), "r"(m));
    return r;
}

// ---------------- mma.sync (base sm_80+ feature; OK on plain sm_100) -----
__device__ __forceinline__ void mma_16n8k8(float d[4], const uint a[2], uint b) {
    asm volatile(
        "mma.sync.aligned.m16n8k8.row.col.f32.bf16.bf16.f32 "
        "{%0,%1,%2,%3}, {%4,%5}, {%6}, {%0,%1,%2,%3};"
        : "+f"(d[0]), "+f"(d[1]), "+f"(d[2]), "+f"(d[3])
        : "r"(a[0]), "r"(a[1]), "r"(b));
}
__device__ __forceinline__ void mma_16n8k16(float d[4], const uint a[4], uint b0, uint b1) {
    asm volatile(
        "mma.sync.aligned.m16n8k16.row.col.f32.bf16.bf16.f32 "
        "{%0,%1,%2,%3}, {%4,%5,%6,%7}, {%8,%9}, {%0,%1,%2,%3};"
        : "+f"(d[0]), "+f"(d[1]), "+f"(d[2]), "+f"(d[3])
        : "r"(a[0]), "r"(a[1]), "r"(a[2]), "r"(a[3]), "r"(b0), "r"(b1));
}

// =========================================================================
// Kernel 1: 1x1 conv projections + 2x2 maxpool -> bf16 outputs.
// =========================================================================
__global__ void __launch_bounds__(128, 1)
proj_kernel(const float* __restrict__ x,
            const float* __restrict__ tw,
            const float* __restrict__ pw,
            const float* __restrict__ gw)
{
    __shared__ float ws[64 * 48];
    for (int i = threadIdx.x; i < 64 * 48; i += 128) {
        int k = i / 48, o = i % 48;
        float v;
        if (o < 8)        v = tw[o * 64 + k];
        else if (o < 16)  v = pw[(o - 8) * 64 + k];
        else              v = gw[(o - 16) * 64 + k];
        ws[i] = v;
    }
    __syncthreads();

    int p  = blockIdx.x * 128 + threadIdx.x;
    int b  = p >> 10;
    int pp = p & 1023;
    int hp = pp >> 5, wp = pp & 31;

    const float* xb = x + (size_t)b * CC * NN;

    float best[40];
#pragma unroll
    for (int c = 0; c < 40; c++) best[c] = -1e30f;

    for (int dy = 0; dy < 2; dy++) {
        ull acc0[24], acc1[24];
#pragma unroll
        for (int c = 0; c < 24; c++) { acc0[c] = 0ull; acc1[c] = 0ull; }

        const float* xrow = xb + (2 * hp + dy) * 64 + 2 * wp;
#pragma unroll 4
        for (int k = 0; k < 64; k++) {
            float2 xv = *(const float2*)(xrow + (size_t)k * NN);
            ull a0 = pack2(xv.x, xv.x);
            ull a1 = pack2(xv.y, xv.y);
            const ull* w2 = (const ull*)(ws + k * 48);
#pragma unroll
            for (int c = 0; c < 24; c++) {
                ull w = w2[c];
                fma2(acc0[c], a0, w);
                fma2(acc1[c], a1, w);
            }
        }

        int n0 = (2 * hp + dy) * 64 + 2 * wp;
        {   // theta -> bf16 pre-scaled by log2(e)
            float u, v; uint4 q;
            unpack2(acc0[0], u, v); q.x = bf2(u * L2E, v * L2E);
            unpack2(acc0[1], u, v); q.y = bf2(u * L2E, v * L2E);
            unpack2(acc0[2], u, v); q.z = bf2(u * L2E, v * L2E);
            unpack2(acc0[3], u, v); q.w = bf2(u * L2E, v * L2E);
            *(uint4*)(g_theta_b + ((size_t)b * NN + n0) * 8) = q;
            unpack2(acc1[0], u, v); q.x = bf2(u * L2E, v * L2E);
            unpack2(acc1[1], u, v); q.y = bf2(u * L2E, v * L2E);
            unpack2(acc1[2], u, v); q.z = bf2(u * L2E, v * L2E);
            unpack2(acc1[3], u, v); q.w = bf2(u * L2E, v * L2E);
            *(uint4*)(g_theta_b + ((size_t)b * NN + n0 + 1) * 8) = q;
        }
#pragma unroll
        for (int c = 4; c < 24; c++) {
            float u, v;
            unpack2(acc0[c], u, v);
            best[2 * c - 8]     = fmaxf(best[2 * c - 8], u);
            best[2 * c - 8 + 1] = fmaxf(best[2 * c - 8 + 1], v);
            unpack2(acc1[c], u, v);
            best[2 * c - 8]     = fmaxf(best[2 * c - 8], u);
            best[2 * c - 8 + 1] = fmaxf(best[2 * c - 8 + 1], v);
        }
    }

    {   // phi bf16 [b][pp][8]
        uint4 q;
        q.x = bf2(best[0], best[1]); q.y = bf2(best[2], best[3]);
        q.z = bf2(best[4], best[5]); q.w = bf2(best[6], best[7]);
        *(uint4*)(g_phi_b + ((size_t)b * NP + pp) * 8) = q;
    }
    {   // g transposed bf16 [b][ch][pp]
#pragma unroll
        for (int c = 0; c < 32; c++)
            g_gT_b[((size_t)b * 32 + c) * NP + pp] = __float2bfloat16(best[8 + c]);
    }
}

// =========================================================================
// Kernel 2: mma.sync flash attention + o-projection + residual.
// Grid (8 tiles, 16 batches), 256 threads (8 warps). Warp owns 64 queries
// (4 m16 tiles); loops 64 chunks of 16 keys:
//   GEMM1 m16n8k8:  S(16qx8k) = theta x phi   (K = 8 channels, exact)
//   softmax: ex2 -> den, pack c-frag -> a-frag (FA2 identity)
//   GEMM2 m16n8k16: A(16qx8ch) += P x gT      (g pre-packed b-frag order)
// Then attn -> smem, f32x2 o_w epilogue + residual.
// =========================================================================
#define THREADS 256
#define SM_PHI   0                    // 1024 x 16B bf16        = 16384
#define SM_GB    16384                // 64kc x 4nt x 32 x 8B   = 65536
#define SM_OW    (16384 + 65536)      // 64 x 32 f32            = 8192
#define SM_DEN   (16384 + 65536 + 8192)            // 512 f32   = 2048
#define SM_ATT   (16384 + 65536 + 8192 + 2048)     // 512 x 34 f32 = 69632
#define SMEM_BYTES (16384 + 65536 + 8192 + 2048 + 69632)
#define ATT_STRIDE 34

__global__ void __launch_bounds__(THREADS, 1)
attn_kernel(const float* __restrict__ x,
            const float* __restrict__ ow,
            const float* __restrict__ gamma_p,
            float* __restrict__ out)
{
    extern __shared__ char sm[];
    const int tid  = threadIdx.x;
    const int wid  = tid >> 5;
    const int lane = tid & 31;
    const int g    = lane >> 2;      // groupID
    const int tig  = lane & 3;       // thread-in-group
    const int b    = blockIdx.y;
    const int tile = blockIdx.x;

    // ---- stage phi [key][8ch] bf16 ----
    {
        const uint4* src = (const uint4*)(g_phi_b + (size_t)b * NP * 8);
        uint4* dst = (uint4*)(sm + SM_PHI);
        for (int i = tid; i < 1024; i += THREADS) dst[i] = src[i];
    }
    // ---- stage gB in b-frag order: [kc][nt][lane] = (b0|b1<<32) ----
    {
        const __nv_bfloat16* gT = g_gT_b + (size_t)b * 32 * NP;
        ull* dst = (ull*)(sm + SM_GB);
        for (int idx = tid; idx < 64 * 4 * 32; idx += THREADS) {
            int ln = idx & 31, nt = (idx >> 5) & 3, kc = idx >> 7;
            int ch = nt * 8 + (ln >> 2);
            const __nv_bfloat16* row = gT + (size_t)ch * NP + kc * 16 + 2 * (ln & 3);
            uint lo = *(const uint*)row;        // keys 2tig, 2tig+1
            uint hi = *(const uint*)(row + 8);  // keys 2tig+8, 2tig+9
            dst[idx] = (ull)lo | ((ull)hi << 32);
        }
    }
    // ---- stage ow (f32) ----
    {
        const float4* src = (const float4*)ow;
        float4* dst = (float4*)(sm + SM_OW);
        for (int i = tid; i < 512; i += THREADS) dst[i] = src[i];
    }
    __syncthreads();

    // ---- theta a-frags: 4 q-tiles of 16 rows ----
    const int wq = tile * 512 + wid * 64;      // warp's first query (global n)
    uint ta[4][2];
#pragma unroll
    for (int qt = 0; qt < 4; qt++) {
        const __nv_bfloat16* t0 = g_theta_b + ((size_t)b * NN + wq + qt * 16 + g) * 8 + 2 * tig;
        ta[qt][0] = *(const uint*)t0;
        ta[qt][1] = *(const uint*)(t0 + 64);   // row +8 -> +8*8 elements
    }

    float aoc[4][4][4];
#pragma unroll
    for (int qt = 0; qt < 4; qt++)
#pragma unroll
        for (int nt = 0; nt < 4; nt++)
#pragma unroll
            for (int r = 0; r < 4; r++) aoc[qt][nt][r] = 0.f;
    float dn[4][2];
#pragma unroll
    for (int qt = 0; qt < 4; qt++) { dn[qt][0] = 0.f; dn[qt][1] = 0.f; }

    const char* phiS = sm + SM_PHI;
    const ull*  gB   = (const ull*)(sm + SM_GB);

    for (int kc = 0; kc < 64; kc++) {
        uint pa[4][4];
        // GEMM1 + softmax for the two 8-key subtiles
#pragma unroll
        for (int kb = 0; kb < 2; kb++) {
            uint pb = *(const uint*)(phiS + (kc * 16 + kb * 8 + g) * 16 + tig * 4);
#pragma unroll
            for (int qt = 0; qt < 4; qt++) {
                float s[4] = {0.f, 0.f, 0.f, 0.f};
                mma_16n8k8(s, ta[qt], pb);
                float e0 = ex2f(s[0]), e1 = ex2f(s[1]);
                float e2 = ex2f(s[2]), e3 = ex2f(s[3]);
                dn[qt][0] += e0 + e1;
                dn[qt][1] += e2 + e3;
                pa[qt][kb * 2 + 0] = bf2(e0, e1);   // (q=g,   k=2tig..+1)
                pa[qt][kb * 2 + 1] = bf2(e2, e3);   // (q=g+8, k=2tig..+1)
            }
        }
        // GEMM2: A += P x gT
#pragma unroll
        for (int nt = 0; nt < 4; nt++) {
            ull bb = gB[(kc * 4 + nt) * 32 + lane];
            uint b0 = (uint)bb, b1 = (uint)(bb >> 32);
#pragma unroll
            for (int qt = 0; qt < 4; qt++)
                mma_16n8k16(aoc[qt][nt], pa[qt], b0, b1);
        }
    }

    // ---- den reduce (over tig lanes) + store attn/den to smem ----
    float* denS = (float*)(sm + SM_DEN);
    float* attS = (float*)(sm + SM_ATT);
    const int wqp = wid * 64;                  // warp's query offset within tile
#pragma unroll
    for (int qt = 0; qt < 4; qt++) {
        float d0 = dn[qt][0]; d0 += shflx(d0, 1); d0 += shflx(d0, 2);
        float d1 = dn[qt][1]; d1 += shflx(d1, 1); d1 += shflx(d1, 2);
        if (tig == 0) {
            denS[wqp + qt * 16 + g]     = d0;
            denS[wqp + qt * 16 + g + 8] = d1;
        }
#pragma unroll
        for (int nt = 0; nt < 4; nt++) {
            int q0 = wqp + qt * 16 + g;
            int ch = nt * 8 + 2 * tig;
            *(float2*)(attS + (size_t)q0 * ATT_STRIDE + ch) =
                make_float2(aoc[qt][nt][0], aoc[qt][nt][1]);
            *(float2*)(attS + (size_t)(q0 + 8) * ATT_STRIDE + ch) =
                make_float2(aoc[qt][nt][2], aoc[qt][nt][3]);
        }
    }
    __syncthreads();

    // ---- epilogue: o = ow x attn ; out = (gamma/den) * o + x ----
    const float gamma = *gamma_p;
    const ulonglong2* ow4 = (const ulonglong2*)(sm + SM_OW);   // [j][8]
#pragma unroll
    for (int jq = 0; jq < 2; jq++) {
        const int p = tid + jq * THREADS;           // query within tile [0,512)
        ull am[16];
        const ull* ap = (const ull*)(attS + (size_t)p * ATT_STRIDE);
#pragma unroll
        for (int c = 0; c < 16; c++) am[c] = ap[c];
        const float sc = gamma / denS[p];

        const int q = tile * 512 + p;
        const float* xq = x + (size_t)b * CC * NN + q;
        float*       oq = out + (size_t)b * CC * NN + q;
        for (int j = 0; j < 64; j++) {
            const ulonglong2* wj = ow4 + j * 8;
            ulonglong2 w0 = wj[0];
            ull o2 = mul2(w0.x, am[0]);
            fma2(o2, w0.y, am[1]);
#pragma unroll
            for (int k = 1; k < 8; k++) {
                ulonglong2 wk = wj[k];
                fma2(o2, wk.x, am[2 * k]);
                fma2(o2, wk.y, am[2 * k + 1]);
            }
            float oa, ob;
            unpack2(o2, oa, ob);
            oq[(size_t)j * NN] = fmaf(sc, oa + ob, xq[(size_t)j * NN]);
        }
    }
}

// =========================================================================
extern "C" void kernel_launch(void* const* d_in, const int* in_sizes, int n_in,
                              void* d_out, int out_size)
{
    const float* x     = (const float*)d_in[0];
    const float* tw    = (const float*)d_in[1];
    const float* pw    = (const float*)d_in[2];
    const float* gw    = (const float*)d_in[3];
    const float* ow    = (const float*)d_in[4];
    const float* gamma = (const float*)d_in[5];
    float* out = (float*)d_out;

    cudaFuncSetAttribute(attn_kernel,
                         cudaFuncAttributeMaxDynamicSharedMemorySize, SMEM_BYTES);

    proj_kernel<<<BB * NP / 128, 128>>>(x, tw, pw, gw);
    attn_kernel<<<dim3(8, BB), THREADS, SMEM_BYTES>>>(x, ow, gamma, out);
}